// round 2
// baseline (speedup 1.0000x reference)
#include <cuda_runtime.h>

// ---------------- problem constants ----------------
#define B_   1024
#define S_   200
#define D_   64
#define NI_  4
#define E_   256            // NI * D
#define INTEREST_ELEMS (B_ * NI_ * D_)   // 262144, adj follows at this offset

// ---------------- device scratch (static; no runtime alloc) ----------------
__device__ float g_uprof[B_ * D_];                       // 256 KB
__device__ float g_item[(long long)B_ * S_ * D_];        // 52.4 MB
__device__ float g_hat [(long long)B_ * S_ * E_];        // 209.7 MB

// ====================================================================
// K1: user profile  uprof[b,d] = 0.25*(ue[uid]+gt[gender]+at[age]+ot[occup])
// ====================================================================
__global__ __launch_bounds__(256) void uprof_kernel(
    const int* __restrict__ uid, const int* __restrict__ age,
    const int* __restrict__ gender, const int* __restrict__ occup,
    const float* __restrict__ ue, const float* __restrict__ at,
    const float* __restrict__ gt, const float* __restrict__ ot)
{
    int idx = blockIdx.x * 256 + threadIdx.x;        // B*D = 65536 threads
    int b = idx >> 6, d = idx & 63;
    float v = ue[(size_t)uid[b]    * 64 + d]
            + gt[(size_t)gender[b] * 64 + d]
            + at[(size_t)age[b]    * 64 + d]
            + ot[(size_t)occup[b]  * 64 + d];
    g_uprof[idx] = 0.25f * v;
}

// ====================================================================
// K2: item_his = mid_emb[mid_his]*mask
// ====================================================================
__global__ __launch_bounds__(256) void gather_kernel(
    const int* __restrict__ mid_his, const float* __restrict__ mask,
    const float* __restrict__ mid_emb)
{
    int t  = blockIdx.x * 256 + threadIdx.x;         // B*S*16 threads (float4)
    int bs = t >> 4, q = t & 15;
    int mi = mid_his[bs];
    float m = mask[bs];
    float4 e = ((const float4*)mid_emb)[(size_t)mi * 16 + q];
    float4 it;
    it.x = e.x * m;  it.y = e.y * m;  it.z = e.z * m;  it.w = e.w * m;
    ((float4*)g_item)[(size_t)bs * 16 + q] = it;
}

// ====================================================================
// K3: adj[b,i,j] = sigmoid( sum_d (item[b,i,d]*uprof[b,d]) * item[b,j,d] )
//                  * mask_i * mask_j
//     64x64 tile, 256 threads, 4x4 micro-tile; uprof folded into A-tile fill.
// ====================================================================
__global__ __launch_bounds__(256) void adj_kernel(
    const float* __restrict__ mask, float* __restrict__ out)
{
    const int b  = blockIdx.z;
    const int i0 = blockIdx.y * 64;
    const int j0 = blockIdx.x * 64;
    __shared__ float As[64][68];   // pad 68: float4-aligned rows, <=2-way conflicts
    __shared__ float Bs[64][68];
    const int tid = threadIdx.x;
    const float* It = g_item + (size_t)b * (S_ * D_);

    #pragma unroll
    for (int p = 0; p < 4; ++p) {
        int q = tid + p * 256;            // 0..1023 float4 slots
        int r = q >> 4, g = q & 15;
        float4 up = ((const float4*)g_uprof)[b * 16 + g];
        float4 av = make_float4(0.f,0.f,0.f,0.f);
        float4 bv = make_float4(0.f,0.f,0.f,0.f);
        if (i0 + r < S_) {
            float4 iv = *(const float4*)(It + (size_t)(i0 + r) * 64 + g * 4);
            av.x = iv.x * up.x; av.y = iv.y * up.y;
            av.z = iv.z * up.z; av.w = iv.w * up.w;
        }
        if (j0 + r < S_) bv = *(const float4*)(It + (size_t)(j0 + r) * 64 + g * 4);
        *(float4*)(&As[r][g * 4]) = av;
        *(float4*)(&Bs[r][g * 4]) = bv;
    }
    __syncthreads();

    const int tx = tid & 15, ty = tid >> 4;
    float acc[4][4] = {};
    #pragma unroll
    for (int k = 0; k < 64; k += 4) {
        float4 a[4], bb[4];
        #pragma unroll
        for (int c = 0; c < 4; ++c) a[c]  = *(const float4*)(&As[ty + 16 * c][k]);
        #pragma unroll
        for (int c = 0; c < 4; ++c) bb[c] = *(const float4*)(&Bs[tx + 16 * c][k]);
        #pragma unroll
        for (int ci = 0; ci < 4; ++ci)
            #pragma unroll
            for (int cj = 0; cj < 4; ++cj)
                acc[ci][cj] += a[ci].x * bb[cj].x + a[ci].y * bb[cj].y
                             + a[ci].z * bb[cj].z + a[ci].w * bb[cj].w;
    }

    const float* mrow = mask + b * S_;
    float* outb = out + (size_t)b * (S_ * S_);
    #pragma unroll
    for (int ci = 0; ci < 4; ++ci) {
        int i = i0 + ty + 16 * ci;
        if (i >= S_) continue;
        float mi = mrow[i];
        #pragma unroll
        for (int cj = 0; cj < 4; ++cj) {
            int j = j0 + tx + 16 * cj;
            if (j >= S_) continue;
            float x = acc[ci][cj];
            float sg = 1.0f / (1.0f + __expf(-x));
            outb[(size_t)i * S_ + j] = sg * mi * mrow[j];
        }
    }
}

// ====================================================================
// K4: hat[b,s,e] = sum_d item[b,s,d] * w[s,e,d]   (per-s GEMM 1024x256x64)
// ====================================================================
__global__ __launch_bounds__(256) void hat_kernel(const float* __restrict__ w)
{
    const int s  = blockIdx.z;
    const int b0 = blockIdx.y * 64;
    const int e0 = blockIdx.x * 64;
    __shared__ float As[64][68];
    __shared__ float Bs[64][68];
    const int tid = threadIdx.x;

    #pragma unroll
    for (int p = 0; p < 4; ++p) {
        int q = tid + p * 256;
        int r = q >> 4, g = q & 15;
        float4 av = *(const float4*)(g_item + ((size_t)(b0 + r) * S_ + s) * 64 + g * 4);
        float4 bv = *(const float4*)(w + ((size_t)s * E_ + (e0 + r)) * 64 + g * 4);
        *(float4*)(&As[r][g * 4]) = av;
        *(float4*)(&Bs[r][g * 4]) = bv;
    }
    __syncthreads();

    const int tx = tid & 15, ty = tid >> 4;
    float acc[4][4] = {};
    #pragma unroll
    for (int k = 0; k < 64; k += 4) {
        float4 a[4], bb[4];
        #pragma unroll
        for (int c = 0; c < 4; ++c) a[c]  = *(const float4*)(&As[ty + 16 * c][k]);
        #pragma unroll
        for (int c = 0; c < 4; ++c) bb[c] = *(const float4*)(&Bs[tx + 16 * c][k]);
        #pragma unroll
        for (int ci = 0; ci < 4; ++ci)
            #pragma unroll
            for (int cj = 0; cj < 4; ++cj)
                acc[ci][cj] += a[ci].x * bb[cj].x + a[ci].y * bb[cj].y
                             + a[ci].z * bb[cj].z + a[ci].w * bb[cj].w;
    }

    #pragma unroll
    for (int ci = 0; ci < 4; ++ci) {
        int bi = b0 + ty + 16 * ci;
        #pragma unroll
        for (int cj = 0; cj < 4; ++cj) {
            int e = e0 + tx + 16 * cj;
            g_hat[((size_t)bi * S_ + s) * E_ + e] = acc[ci][cj];
        }
    }
}

// ====================================================================
// K5: dynamic routing, fully fused. One block per b; hat[b] (200x256,
//     padded to 257) lives in dynamic smem -> hat read from HBM once.
// ====================================================================
#define HPAD 257
__global__ __launch_bounds__(256) void route_kernel(
    const float* __restrict__ mask, float* __restrict__ out_interest)
{
    extern __shared__ float hat_s[];                 // [200][257]
    __shared__ float cw_s[NI_ * S_];
    __shared__ float sw_s[NI_ * S_];
    __shared__ float cap_s[E_];
    __shared__ float msk[S_];
    __shared__ float wsum[8];

    const int b = blockIdx.x;
    const int tid = threadIdx.x;

    // load hat[b] (51200 floats) coalesced, store padded
    const float4* src = (const float4*)(g_hat + (size_t)b * S_ * E_);
    for (int x4 = tid; x4 < S_ * E_ / 4; x4 += 256) {
        int s = x4 >> 6;                 // 64 float4 per row
        int e4 = (x4 & 63) * 4;
        float4 v = src[x4];
        float* dst = &hat_s[s * HPAD + e4];
        dst[0] = v.x; dst[1] = v.y; dst[2] = v.z; dst[3] = v.w;
    }
    if (tid < S_) msk[tid] = mask[b * S_ + tid];
    for (int x = tid; x < NI_ * S_; x += 256) cw_s[x] = 0.f;
    __syncthreads();

    const int k = tid >> 6, d = tid & 63;
    float capv = 0.f;

    for (int it = 0; it < 3; ++it) {
        // sw = softmax over k, masked
        if (tid < S_) {
            float c0 = cw_s[0 * S_ + tid], c1 = cw_s[1 * S_ + tid];
            float c2 = cw_s[2 * S_ + tid], c3 = cw_s[3 * S_ + tid];
            float mx = fmaxf(fmaxf(c0, c1), fmaxf(c2, c3));
            float e0 = __expf(c0 - mx), e1 = __expf(c1 - mx);
            float e2 = __expf(c2 - mx), e3 = __expf(c3 - mx);
            float inv = 1.0f / (e0 + e1 + e2 + e3);
            float mm = (msk[tid] == 0.f) ? 0.f : inv;
            sw_s[0 * S_ + tid] = e0 * mm;
            sw_s[1 * S_ + tid] = e1 * mm;
            sw_s[2 * S_ + tid] = e2 * mm;
            sw_s[3 * S_ + tid] = e3 * mm;
        }
        __syncthreads();

        // v[k,d] = sum_s sw[k,s]*hat[k,s,d]
        float v = 0.f;
        const float* swk = &sw_s[k * S_];
        for (int s = 0; s < S_; ++s)
            v += swk[s] * hat_s[s * HPAD + k * 64 + d];

        // squash: n = |v|^2 over d (64 threads = 2 warps per k)
        float p = v * v;
        #pragma unroll
        for (int o = 16; o; o >>= 1) p += __shfl_xor_sync(0xffffffffu, p, o);
        if ((tid & 31) == 0) wsum[tid >> 5] = p;
        __syncthreads();
        float n = wsum[2 * k] + wsum[2 * k + 1];
        float scale = n / (1.0f + n) / sqrtf(n + 1e-9f);
        capv = scale * v;
        cap_s[tid] = capv;
        __syncthreads();

        if (it < 2) {
            // cw[k,s] += hat[k,s,:] . cap[k,:]
            for (int idx = tid; idx < NI_ * S_; idx += 256) {
                int kk = idx / S_, s = idx - kk * S_;
                const float* hr = &hat_s[s * HPAD + kk * 64];
                const float* cr = &cap_s[kk * 64];
                float dsum = 0.f;
                #pragma unroll 8
                for (int dd = 0; dd < 64; ++dd) dsum += hr[dd] * cr[dd];
                cw_s[idx] += dsum;
            }
            __syncthreads();
        }
    }

    out_interest[(size_t)b * E_ + tid] = capv;
}

// ====================================================================
// launch
// ====================================================================
extern "C" void kernel_launch(void* const* d_in, const int* in_sizes, int n_in,
                              void* d_out, int out_size)
{
    const int*   uid      = (const int*)  d_in[0];
    const int*   age      = (const int*)  d_in[1];
    const int*   gender   = (const int*)  d_in[2];
    const int*   occup    = (const int*)  d_in[3];
    const int*   mid_his  = (const int*)  d_in[4];
    const float* mask     = (const float*)d_in[5];
    const float* ue       = (const float*)d_in[6];
    const float* at       = (const float*)d_in[7];
    const float* gt       = (const float*)d_in[8];
    const float* ot       = (const float*)d_in[9];
    const float* mid_emb  = (const float*)d_in[10];
    const float* w        = (const float*)d_in[11];
    float* out = (float*)d_out;

    const int route_smem = S_ * HPAD * 4;   // 205600 B
    cudaFuncSetAttribute(route_kernel, cudaFuncAttributeMaxDynamicSharedMemorySize,
                         route_smem);

    uprof_kernel<<<B_ * D_ / 256, 256>>>(uid, age, gender, occup, ue, at, gt, ot);
    gather_kernel<<<B_ * S_ * 16 / 256, 256>>>(mid_his, mask, mid_emb);
    adj_kernel<<<dim3(4, 4, B_), 256>>>(mask, out + INTEREST_ELEMS);
    hat_kernel<<<dim3(E_ / 64, B_ / 64, S_), 256>>>(w);
    route_kernel<<<B_, 256, route_smem>>>(mask, out);
}

// round 4
// speedup vs baseline: 1.7797x; 1.7797x over previous
#include <cuda_runtime.h>
#include <cstdint>

// ---------------- problem constants ----------------
#define B_   1024
#define S_   200
#define D_   64
#define NI_  4
#define E_   256            // NI * D
#define INTEREST_ELEMS (B_ * NI_ * D_)   // 262144, adj follows at this offset

// ---------------- device scratch (static; no runtime alloc) ----------------
__device__ float g_uprof[B_ * D_];                       // 256 KB
__device__ float g_item[(long long)B_ * S_ * D_];        // 52.4 MB
__device__ float g_hat [(long long)B_ * S_ * E_];        // 209.7 MB

// ---------------- tf32 mma helpers ----------------
__device__ __forceinline__ uint32_t f2tf(float x) {
    uint32_t u;
    asm("cvt.rna.tf32.f32 %0, %1;" : "=r"(u) : "f"(x));
    return u;
}

__device__ __forceinline__ void mma8(float* d, const uint32_t* a,
                                     uint32_t b0, uint32_t b1) {
    asm volatile(
        "mma.sync.aligned.m16n8k8.row.col.f32.tf32.tf32.f32 "
        "{%0,%1,%2,%3}, {%4,%5,%6,%7}, {%8,%9}, {%0,%1,%2,%3};"
        : "+f"(d[0]), "+f"(d[1]), "+f"(d[2]), "+f"(d[3])
        : "r"(a[0]), "r"(a[1]), "r"(a[2]), "r"(a[3]), "r"(b0), "r"(b1));
}

#define LDA 68     // smem row stride (uint32); bank = (4g+t) -> conflict-free
#define SMEM_GEMM_BYTES (2 * 128 * LDA * 4)   // 69632

// Shared mma mainloop: block tile 128x128, K=64, 8 warps of 32x64.
// acc[mf][nf][c] layout per PTX m16n8k8 fragment spec.
__device__ __forceinline__ void mma_core(const uint32_t* __restrict__ As,
                                         const uint32_t* __restrict__ Bs,
                                         int tid, float acc[2][8][4]) {
    const int lane = tid & 31, wid = tid >> 5;
    const int g = lane >> 2, t = lane & 3;
    const int m0 = (wid & 3) * 32, n0 = (wid >> 2) * 64;
    #pragma unroll
    for (int k0 = 0; k0 < 64; k0 += 8) {
        uint32_t a[2][4];
        #pragma unroll
        for (int mf = 0; mf < 2; ++mf) {
            const uint32_t* p = As + (m0 + 16 * mf + g) * LDA + k0 + t;
            a[mf][0] = p[0];
            a[mf][1] = p[8 * LDA];
            a[mf][2] = p[4];
            a[mf][3] = p[8 * LDA + 4];
        }
        #pragma unroll
        for (int nf = 0; nf < 8; ++nf) {
            const uint32_t* p = Bs + (n0 + 8 * nf + g) * LDA + k0 + t;
            uint32_t b0v = p[0], b1v = p[4];
            mma8(acc[0][nf], a[0], b0v, b1v);
            mma8(acc[1][nf], a[1], b0v, b1v);
        }
    }
}

// ====================================================================
// K1: user profile
// ====================================================================
__global__ __launch_bounds__(256) void uprof_kernel(
    const int* __restrict__ uid, const int* __restrict__ age,
    const int* __restrict__ gender, const int* __restrict__ occup,
    const float* __restrict__ ue, const float* __restrict__ at,
    const float* __restrict__ gt, const float* __restrict__ ot)
{
    int idx = blockIdx.x * 256 + threadIdx.x;
    int b = idx >> 6, d = idx & 63;
    float v = ue[(size_t)uid[b]    * 64 + d]
            + gt[(size_t)gender[b] * 64 + d]
            + at[(size_t)age[b]    * 64 + d]
            + ot[(size_t)occup[b]  * 64 + d];
    g_uprof[idx] = 0.25f * v;
}

// ====================================================================
// K2: item_his = mid_emb[mid_his]*mask
// ====================================================================
__global__ __launch_bounds__(256) void gather_kernel(
    const int* __restrict__ mid_his, const float* __restrict__ mask,
    const float* __restrict__ mid_emb)
{
    int t  = blockIdx.x * 256 + threadIdx.x;
    int bs = t >> 4, q = t & 15;
    int mi = mid_his[bs];
    float m = mask[bs];
    float4 e = ((const float4*)mid_emb)[(size_t)mi * 16 + q];
    float4 it;
    it.x = e.x * m;  it.y = e.y * m;  it.z = e.z * m;  it.w = e.w * m;
    ((float4*)g_item)[(size_t)bs * 16 + q] = it;
}

// ====================================================================
// K3: adj — tensor-core tf32. A = item*uprof (fold), B = item.
//     tile 128x128, grid (2,2,B)
// ====================================================================
__global__ __launch_bounds__(256) void adj_kernel(
    const float* __restrict__ mask, float* __restrict__ out)
{
    extern __shared__ uint32_t sh[];
    uint32_t* As = sh;
    uint32_t* Bs = sh + 128 * LDA;
    __shared__ float msk[256];

    const int b  = blockIdx.z;
    const int i0 = blockIdx.y * 128;
    const int j0 = blockIdx.x * 128;
    const int tid = threadIdx.x;
    const float* It = g_item + (size_t)b * (S_ * D_);

    msk[tid] = (tid < S_) ? mask[b * S_ + tid] : 0.f;

    #pragma unroll
    for (int p = 0; p < 8; ++p) {
        int q = tid + p * 256;            // 2048 float4 slots per tile
        int r = q >> 4, c4 = q & 15;
        float4 up = ((const float4*)g_uprof)[b * 16 + c4];
        float4 av = make_float4(0.f, 0.f, 0.f, 0.f);
        float4 bv = make_float4(0.f, 0.f, 0.f, 0.f);
        if (i0 + r < S_) {
            float4 iv = *(const float4*)(It + (size_t)(i0 + r) * 64 + c4 * 4);
            av.x = iv.x * up.x; av.y = iv.y * up.y;
            av.z = iv.z * up.z; av.w = iv.w * up.w;
        }
        if (j0 + r < S_) bv = *(const float4*)(It + (size_t)(j0 + r) * 64 + c4 * 4);
        uint4 at4 = make_uint4(f2tf(av.x), f2tf(av.y), f2tf(av.z), f2tf(av.w));
        uint4 bt4 = make_uint4(f2tf(bv.x), f2tf(bv.y), f2tf(bv.z), f2tf(bv.w));
        *(uint4*)(As + r * LDA + c4 * 4) = at4;
        *(uint4*)(Bs + r * LDA + c4 * 4) = bt4;
    }
    __syncthreads();

    float acc[2][8][4] = {};
    mma_core(As, Bs, tid, acc);

    const int lane = tid & 31, wid = tid >> 5;
    const int g = lane >> 2, t = lane & 3;
    const int m0 = (wid & 3) * 32, n0 = (wid >> 2) * 64;
    float* outb = out + (size_t)b * (S_ * S_);

    #pragma unroll
    for (int mf = 0; mf < 2; ++mf) {
        #pragma unroll
        for (int nf = 0; nf < 8; ++nf) {
            int i = i0 + m0 + 16 * mf + g;
            int j = j0 + n0 + 8 * nf + 2 * t;          // even; j+1 <= 199 iff j < 200
            if (j < S_) {
                float mj0 = msk[j], mj1 = msk[j + 1];
                if (i < S_) {
                    float mi = msk[i];
                    float s0 = 1.f / (1.f + __expf(-acc[mf][nf][0]));
                    float s1 = 1.f / (1.f + __expf(-acc[mf][nf][1]));
                    *(float2*)(outb + (size_t)i * S_ + j) =
                        make_float2(s0 * mi * mj0, s1 * mi * mj1);
                }
                if (i + 8 < S_) {
                    float mi = msk[i + 8];
                    float s2 = 1.f / (1.f + __expf(-acc[mf][nf][2]));
                    float s3 = 1.f / (1.f + __expf(-acc[mf][nf][3]));
                    *(float2*)(outb + (size_t)(i + 8) * S_ + j) =
                        make_float2(s2 * mi * mj0, s3 * mi * mj1);
                }
            }
        }
    }
}

// ====================================================================
// K4: hat — tensor-core tf32. A = item[:,s,:], B = w[s] (N x K).
//     tile 128x128, grid (2, 8, S)
// ====================================================================
__global__ __launch_bounds__(256) void hat_kernel(const float* __restrict__ w)
{
    extern __shared__ uint32_t sh[];
    uint32_t* As = sh;
    uint32_t* Bs = sh + 128 * LDA;

    const int s  = blockIdx.z;
    const int b0 = blockIdx.y * 128;
    const int e0 = blockIdx.x * 128;
    const int tid = threadIdx.x;

    #pragma unroll
    for (int p = 0; p < 8; ++p) {
        int q = tid + p * 256;
        int r = q >> 4, c4 = q & 15;
        float4 av = *(const float4*)(g_item + ((size_t)(b0 + r) * S_ + s) * 64 + c4 * 4);
        float4 bv = *(const float4*)(w + ((size_t)s * E_ + (e0 + r)) * 64 + c4 * 4);
        uint4 at4 = make_uint4(f2tf(av.x), f2tf(av.y), f2tf(av.z), f2tf(av.w));
        uint4 bt4 = make_uint4(f2tf(bv.x), f2tf(bv.y), f2tf(bv.z), f2tf(bv.w));
        *(uint4*)(As + r * LDA + c4 * 4) = at4;
        *(uint4*)(Bs + r * LDA + c4 * 4) = bt4;
    }
    __syncthreads();

    float acc[2][8][4] = {};
    mma_core(As, Bs, tid, acc);

    const int lane = tid & 31, wid = tid >> 5;
    const int g = lane >> 2, t = lane & 3;
    const int m0 = (wid & 3) * 32, n0 = (wid >> 2) * 64;

    #pragma unroll
    for (int mf = 0; mf < 2; ++mf) {
        #pragma unroll
        for (int nf = 0; nf < 8; ++nf) {
            int bi = b0 + m0 + 16 * mf + g;
            int e  = e0 + n0 + 8 * nf + 2 * t;
            *(float2*)(g_hat + ((size_t)bi * S_ + s) * E_ + e) =
                make_float2(acc[mf][nf][0], acc[mf][nf][1]);
            *(float2*)(g_hat + ((size_t)(bi + 8) * S_ + s) * E_ + e) =
                make_float2(acc[mf][nf][2], acc[mf][nf][3]);
        }
    }
}

// ====================================================================
// K5: dynamic routing, fused, 512 threads, hat[b] in smem (read HBM once)
// ====================================================================
#define HPAD 257
__global__ __launch_bounds__(512) void route_kernel(
    const float* __restrict__ mask, float* __restrict__ out_interest)
{
    extern __shared__ float hat_s[];                 // [200][257]
    __shared__ float cw_s[NI_ * S_];
    __shared__ float sw_s[NI_ * S_];
    __shared__ float cap_s[E_];
    __shared__ float msk[S_];
    __shared__ float wsum[16];

    const int b = blockIdx.x;
    const int tid = threadIdx.x;

    const float4* src = (const float4*)(g_hat + (size_t)b * S_ * E_);
    for (int x4 = tid; x4 < S_ * E_ / 4; x4 += 512) {
        int s = x4 >> 6;                 // 64 float4 per row
        int e4 = (x4 & 63) * 4;
        float4 v = src[x4];
        float* dst = &hat_s[s * HPAD + e4];
        dst[0] = v.x; dst[1] = v.y; dst[2] = v.z; dst[3] = v.w;
    }
    if (tid < S_) msk[tid] = mask[b * S_ + tid];
    for (int x = tid; x < NI_ * S_; x += 512) cw_s[x] = 0.f;
    __syncthreads();

    const int k = tid >> 7;           // 0..3
    const int d = (tid >> 1) & 63;    // pair shares d
    const int half = tid & 1;
    const int warpid = tid >> 5;
    float capv = 0.f;

    for (int it = 0; it < 3; ++it) {
        if (tid < S_) {
            float c0 = cw_s[0 * S_ + tid], c1 = cw_s[1 * S_ + tid];
            float c2 = cw_s[2 * S_ + tid], c3 = cw_s[3 * S_ + tid];
            float mx = fmaxf(fmaxf(c0, c1), fmaxf(c2, c3));
            float e0 = __expf(c0 - mx), e1 = __expf(c1 - mx);
            float e2 = __expf(c2 - mx), e3 = __expf(c3 - mx);
            float inv = 1.0f / (e0 + e1 + e2 + e3);
            float mm = (msk[tid] == 0.f) ? 0.f : inv;
            sw_s[0 * S_ + tid] = e0 * mm;
            sw_s[1 * S_ + tid] = e1 * mm;
            sw_s[2 * S_ + tid] = e2 * mm;
            sw_s[3 * S_ + tid] = e3 * mm;
        }
        __syncthreads();

        // v[k,d] = sum_s sw[k,s]*hat[k,s,d]; s-loop split across thread pair
        float v = 0.f;
        const float* swk = &sw_s[k * S_];
        const int sbeg = half * 100;
        for (int s = sbeg; s < sbeg + 100; ++s)
            v += swk[s] * hat_s[s * HPAD + k * 64 + d];
        v += __shfl_xor_sync(0xffffffffu, v, 1);     // both halves hold full sum

        float p = half ? 0.f : v * v;
        #pragma unroll
        for (int o = 16; o; o >>= 1) p += __shfl_xor_sync(0xffffffffu, p, o);
        if ((tid & 31) == 0) wsum[warpid] = p;
        __syncthreads();
        float n = wsum[4 * k] + wsum[4 * k + 1] + wsum[4 * k + 2] + wsum[4 * k + 3];
        float scale = n / (1.0f + n) / sqrtf(n + 1e-9f);
        capv = scale * v;
        if (!half) cap_s[k * 64 + d] = capv;
        __syncthreads();

        if (it < 2) {
            for (int idx = tid; idx < NI_ * S_; idx += 512) {
                int kk = idx / S_, s = idx - kk * S_;
                const float* hr = &hat_s[s * HPAD + kk * 64];
                const float* cr = &cap_s[kk * 64];
                float dsum = 0.f;
                #pragma unroll 8
                for (int dd = 0; dd < 64; ++dd) dsum += hr[dd] * cr[dd];
                cw_s[idx] += dsum;
            }
            __syncthreads();
        }
    }

    if (!half) out_interest[(size_t)b * E_ + k * 64 + d] = capv;
}

// ====================================================================
// launch
// ====================================================================
extern "C" void kernel_launch(void* const* d_in, const int* in_sizes, int n_in,
                              void* d_out, int out_size)
{
    const int*   uid      = (const int*)  d_in[0];
    const int*   age      = (const int*)  d_in[1];
    const int*   gender   = (const int*)  d_in[2];
    const int*   occup    = (const int*)  d_in[3];
    const int*   mid_his  = (const int*)  d_in[4];
    const float* mask     = (const float*)d_in[5];
    const float* ue       = (const float*)d_in[6];
    const float* at       = (const float*)d_in[7];
    const float* gt       = (const float*)d_in[8];
    const float* ot       = (const float*)d_in[9];
    const float* mid_emb  = (const float*)d_in[10];
    const float* w        = (const float*)d_in[11];
    float* out = (float*)d_out;

    const int route_smem = S_ * HPAD * 4;   // 205600 B
    cudaFuncSetAttribute(route_kernel, cudaFuncAttributeMaxDynamicSharedMemorySize,
                         route_smem);
    cudaFuncSetAttribute(adj_kernel, cudaFuncAttributeMaxDynamicSharedMemorySize,
                         SMEM_GEMM_BYTES);
    cudaFuncSetAttribute(hat_kernel, cudaFuncAttributeMaxDynamicSharedMemorySize,
                         SMEM_GEMM_BYTES);

    uprof_kernel<<<B_ * D_ / 256, 256>>>(uid, age, gender, occup, ue, at, gt, ot);
    gather_kernel<<<B_ * S_ * 16 / 256, 256>>>(mid_his, mask, mid_emb);
    adj_kernel<<<dim3(2, 2, B_), 256, SMEM_GEMM_BYTES>>>(mask, out + INTEREST_ELEMS);
    hat_kernel<<<dim3(2, B_ / 128, S_), 256, SMEM_GEMM_BYTES>>>(w);
    route_kernel<<<B_, 512, route_smem>>>(mask, out);
}

// round 7
// speedup vs baseline: 1.8617x; 1.0461x over previous
#include <cuda_runtime.h>
#include <cstdint>

// ---------------- problem constants ----------------
#define B_   1024
#define S_   200
#define D_   64
#define NI_  4
#define E_   256            // NI * D
#define INTEREST_ELEMS (B_ * NI_ * D_)   // 262144, adj follows at this offset

// ---------------- device scratch (static; no runtime alloc) ----------------
__device__ float g_uprof[B_ * D_];                       // 256 KB
__device__ float g_item[(long long)B_ * S_ * D_];        // 52.4 MB
__device__ float g_hat [(long long)B_ * S_ * E_];        // 209.7 MB

// ---------------- tf32 mma helpers ----------------
__device__ __forceinline__ uint32_t f2tf(float x) {
    uint32_t u;
    asm("cvt.rna.tf32.f32 %0, %1;" : "=r"(u) : "f"(x));
    return u;
}

__device__ __forceinline__ void mma8(float* d, const uint32_t* a,
                                     uint32_t b0, uint32_t b1) {
    asm volatile(
        "mma.sync.aligned.m16n8k8.row.col.f32.tf32.tf32.f32 "
        "{%0,%1,%2,%3}, {%4,%5,%6,%7}, {%8,%9}, {%0,%1,%2,%3};"
        : "+f"(d[0]), "+f"(d[1]), "+f"(d[2]), "+f"(d[3])
        : "r"(a[0]), "r"(a[1]), "r"(a[2]), "r"(a[3]), "r"(b0), "r"(b1));
}

#define LDA 68     // smem row stride (uint32); conflict-free fragment LDS
#define SMEM_GEMM_BYTES (2 * 128 * LDA * 4)   // 69632

// 128x128x64 block tile, 8 warps of 32x64 each.
__device__ __forceinline__ void mma_core(const uint32_t* __restrict__ As,
                                         const uint32_t* __restrict__ Bs,
                                         int tid, float acc[2][8][4]) {
    const int lane = tid & 31, wid = tid >> 5;
    const int g = lane >> 2, t = lane & 3;
    const int m0 = (wid & 3) * 32, n0 = (wid >> 2) * 64;
    #pragma unroll
    for (int k0 = 0; k0 < 64; k0 += 8) {
        uint32_t a[2][4];
        #pragma unroll
        for (int mf = 0; mf < 2; ++mf) {
            const uint32_t* p = As + (m0 + 16 * mf + g) * LDA + k0 + t;
            a[mf][0] = p[0];
            a[mf][1] = p[8 * LDA];
            a[mf][2] = p[4];
            a[mf][3] = p[8 * LDA + 4];
        }
        #pragma unroll
        for (int nf = 0; nf < 8; ++nf) {
            const uint32_t* p = Bs + (n0 + 8 * nf + g) * LDA + k0 + t;
            uint32_t b0v = p[0], b1v = p[4];
            mma8(acc[0][nf], a[0], b0v, b1v);
            mma8(acc[1][nf], a[1], b0v, b1v);
        }
    }
}

// ====================================================================
// K1: user profile
// ====================================================================
__global__ __launch_bounds__(256) void uprof_kernel(
    const int* __restrict__ uid, const int* __restrict__ age,
    const int* __restrict__ gender, const int* __restrict__ occup,
    const float* __restrict__ ue, const float* __restrict__ at,
    const float* __restrict__ gt, const float* __restrict__ ot)
{
    int idx = blockIdx.x * 256 + threadIdx.x;
    int b = idx >> 6, d = idx & 63;
    float v = ue[(size_t)uid[b]    * 64 + d]
            + gt[(size_t)gender[b] * 64 + d]
            + at[(size_t)age[b]    * 64 + d]
            + ot[(size_t)occup[b]  * 64 + d];
    g_uprof[idx] = 0.25f * v;
}

// ====================================================================
// K2: item_his = mid_emb[mid_his]*mask
// ====================================================================
__global__ __launch_bounds__(256) void gather_kernel(
    const int* __restrict__ mid_his, const float* __restrict__ mask,
    const float* __restrict__ mid_emb)
{
    int t  = blockIdx.x * 256 + threadIdx.x;
    int bs = t >> 4, q = t & 15;
    int mi = mid_his[bs];
    float m = mask[bs];
    float4 e = ((const float4*)mid_emb)[(size_t)mi * 16 + q];
    float4 it;
    it.x = e.x * m;  it.y = e.y * m;  it.z = e.z * m;  it.w = e.w * m;
    ((float4*)g_item)[(size_t)bs * 16 + q] = it;
}

// ====================================================================
// K3: adj — tf32 tensor cores, tile 128x128, grid (2,2,B)
// ====================================================================
__global__ __launch_bounds__(256) void adj_kernel(
    const float* __restrict__ mask, float* __restrict__ out)
{
    extern __shared__ uint32_t sh[];
    uint32_t* As = sh;
    uint32_t* Bs = sh + 128 * LDA;
    __shared__ float msk[256];

    const int b  = blockIdx.z;
    const int i0 = blockIdx.y * 128;
    const int j0 = blockIdx.x * 128;
    const int tid = threadIdx.x;
    const float* It = g_item + (size_t)b * (S_ * D_);

    msk[tid] = (tid < S_) ? mask[b * S_ + tid] : 0.f;

    #pragma unroll
    for (int p = 0; p < 8; ++p) {
        int q = tid + p * 256;
        int r = q >> 4, c4 = q & 15;
        float4 up = ((const float4*)g_uprof)[b * 16 + c4];
        float4 av = make_float4(0.f, 0.f, 0.f, 0.f);
        float4 bv = make_float4(0.f, 0.f, 0.f, 0.f);
        if (i0 + r < S_) {
            float4 iv = *(const float4*)(It + (size_t)(i0 + r) * 64 + c4 * 4);
            av.x = iv.x * up.x; av.y = iv.y * up.y;
            av.z = iv.z * up.z; av.w = iv.w * up.w;
        }
        if (j0 + r < S_) bv = *(const float4*)(It + (size_t)(j0 + r) * 64 + c4 * 4);
        uint4 at4 = make_uint4(f2tf(av.x), f2tf(av.y), f2tf(av.z), f2tf(av.w));
        uint4 bt4 = make_uint4(f2tf(bv.x), f2tf(bv.y), f2tf(bv.z), f2tf(bv.w));
        *(uint4*)(As + r * LDA + c4 * 4) = at4;
        *(uint4*)(Bs + r * LDA + c4 * 4) = bt4;
    }
    __syncthreads();

    float acc[2][8][4] = {};
    mma_core(As, Bs, tid, acc);

    const int lane = tid & 31, wid = tid >> 5;
    const int g = lane >> 2, t = lane & 3;
    const int m0 = (wid & 3) * 32, n0 = (wid >> 2) * 64;
    float* outb = out + (size_t)b * (S_ * S_);

    #pragma unroll
    for (int mf = 0; mf < 2; ++mf) {
        #pragma unroll
        for (int nf = 0; nf < 8; ++nf) {
            int i = i0 + m0 + 16 * mf + g;
            int j = j0 + n0 + 8 * nf + 2 * t;
            if (j < S_) {
                float mj0 = msk[j], mj1 = msk[j + 1];
                if (i < S_) {
                    float mi = msk[i];
                    float s0 = 1.f / (1.f + __expf(-acc[mf][nf][0]));
                    float s1 = 1.f / (1.f + __expf(-acc[mf][nf][1]));
                    *(float2*)(outb + (size_t)i * S_ + j) =
                        make_float2(s0 * mi * mj0, s1 * mi * mj1);
                }
                if (i + 8 < S_) {
                    float mi = msk[i + 8];
                    float s2 = 1.f / (1.f + __expf(-acc[mf][nf][2]));
                    float s3 = 1.f / (1.f + __expf(-acc[mf][nf][3]));
                    *(float2*)(outb + (size_t)(i + 8) * S_ + j) =
                        make_float2(s2 * mi * mj0, s3 * mi * mj1);
                }
            }
        }
    }
}

// ====================================================================
// K4: hat — tf32 tensor cores, fp32 output. tile 128x128, grid (2,8,S)
// ====================================================================
__global__ __launch_bounds__(256) void hat_kernel(const float* __restrict__ w)
{
    extern __shared__ uint32_t sh[];
    uint32_t* As = sh;
    uint32_t* Bs = sh + 128 * LDA;

    const int s  = blockIdx.z;
    const int b0 = blockIdx.y * 128;
    const int e0 = blockIdx.x * 128;
    const int tid = threadIdx.x;

    #pragma unroll
    for (int p = 0; p < 8; ++p) {
        int q = tid + p * 256;
        int r = q >> 4, c4 = q & 15;
        float4 av = *(const float4*)(g_item + ((size_t)(b0 + r) * S_ + s) * 64 + c4 * 4);
        float4 bv = *(const float4*)(w + ((size_t)s * E_ + (e0 + r)) * 64 + c4 * 4);
        uint4 at4 = make_uint4(f2tf(av.x), f2tf(av.y), f2tf(av.z), f2tf(av.w));
        uint4 bt4 = make_uint4(f2tf(bv.x), f2tf(bv.y), f2tf(bv.z), f2tf(bv.w));
        *(uint4*)(As + r * LDA + c4 * 4) = at4;
        *(uint4*)(Bs + r * LDA + c4 * 4) = bt4;
    }
    __syncthreads();

    float acc[2][8][4] = {};
    mma_core(As, Bs, tid, acc);

    const int lane = tid & 31, wid = tid >> 5;
    const int g = lane >> 2, t = lane & 3;
    const int m0 = (wid & 3) * 32, n0 = (wid >> 2) * 64;

    #pragma unroll
    for (int mf = 0; mf < 2; ++mf) {
        #pragma unroll
        for (int nf = 0; nf < 8; ++nf) {
            int bi = b0 + m0 + 16 * mf + g;
            int e  = e0 + n0 + 8 * nf + 2 * t;
            *(float2*)(g_hat + ((size_t)bi * S_ + s) * E_ + e) =
                make_float2(acc[mf][nf][0], acc[mf][nf][1]);
            *(float2*)(g_hat + ((size_t)(bi + 8) * S_ + s) * E_ + e) =
                make_float2(acc[mf][nf][2], acc[mf][nf][3]);
        }
    }
}

// ====================================================================
// K5: routing, fused, 512 threads, MASK-COMPACTED: only active s rows
//     (mask=1) are loaded into smem and iterated. Exact vs reference
//     (skipped rows contribute exactly 0.0 to every sum).
// ====================================================================
#define HPAD 257
#define ROUTE_SMEM (S_ * HPAD * 4)   // 205600 B
__global__ __launch_bounds__(512) void route_kernel(
    const float* __restrict__ mask, float* __restrict__ out_interest)
{
    extern __shared__ float hat_s[];                 // [nact][257], nact<=200
    __shared__ float cw_s[NI_ * S_];
    __shared__ float sw_s[NI_ * S_];
    __shared__ float cap_s[E_];
    __shared__ float wsum[16];
    __shared__ int   act[S_];
    __shared__ int   wtot[16];
    __shared__ int   nact_s;

    const int b = blockIdx.x;
    const int tid = threadIdx.x;
    const int lane = tid & 31, wrp = tid >> 5;

    // ---- deterministic compaction of active s (mask != 0) ----
    int pred = (tid < S_) ? (mask[b * S_ + tid] != 0.f) : 0;
    unsigned bal = __ballot_sync(0xffffffffu, pred);
    if (lane == 0) wtot[wrp] = __popc(bal);
    __syncthreads();
    int prefix = 0;
    for (int i = 0; i < wrp; ++i) prefix += wtot[i];
    if (pred) act[prefix + __popc(bal & ((1u << lane) - 1u))] = tid;
    if (tid == 0) {
        int t = 0;
        for (int i = 0; i < 7; ++i) t += wtot[i];
        nact_s = t;
    }
    __syncthreads();
    const int nact = nact_s;

    // ---- load only active hat rows (coalesced per row) ----
    const float* hb = g_hat + (size_t)b * S_ * E_;
    for (int x4 = tid; x4 < nact * 64; x4 += 512) {
        int c = x4 >> 6, e4 = (x4 & 63) * 4;
        float4 v = *(const float4*)(hb + (size_t)act[c] * E_ + e4);
        float* dst = &hat_s[c * HPAD + e4];
        dst[0] = v.x; dst[1] = v.y; dst[2] = v.z; dst[3] = v.w;
    }
    for (int x = tid; x < NI_ * S_; x += 512) cw_s[x] = 0.f;
    __syncthreads();

    const int k = tid >> 7;           // 0..3
    const int d = (tid >> 1) & 63;    // pair shares d
    const int half = tid & 1;
    const int off = k * 64 + d;
    const int hn = (nact + 1) >> 1;
    float capv = 0.f;

    for (int it = 0; it < 3; ++it) {
        // softmax over k at each active position (no masking needed)
        if (tid < nact) {
            float c0 = cw_s[0 * S_ + tid], c1 = cw_s[1 * S_ + tid];
            float c2 = cw_s[2 * S_ + tid], c3 = cw_s[3 * S_ + tid];
            float mx = fmaxf(fmaxf(c0, c1), fmaxf(c2, c3));
            float e0 = __expf(c0 - mx), e1 = __expf(c1 - mx);
            float e2 = __expf(c2 - mx), e3 = __expf(c3 - mx);
            float inv = 1.0f / (e0 + e1 + e2 + e3);
            sw_s[0 * S_ + tid] = e0 * inv;
            sw_s[1 * S_ + tid] = e1 * inv;
            sw_s[2 * S_ + tid] = e2 * inv;
            sw_s[3 * S_ + tid] = e3 * inv;
        }
        __syncthreads();

        // v[k,d] = sum_c sw[k,c]*hat[c, k*64+d]; c-range split across pair
        float v = 0.f;
        const float* swk = &sw_s[k * S_];
        const int cbeg = half * hn;
        const int cend = (cbeg + hn < nact) ? cbeg + hn : nact;
        for (int c = cbeg; c < cend; ++c)
            v += swk[c] * hat_s[c * HPAD + off];
        v += __shfl_xor_sync(0xffffffffu, v, 1);     // both halves: full sum

        float p = half ? 0.f : v * v;
        #pragma unroll
        for (int o = 16; o; o >>= 1) p += __shfl_xor_sync(0xffffffffu, p, o);
        if (lane == 0) wsum[wrp] = p;
        __syncthreads();
        float n = wsum[4 * k] + wsum[4 * k + 1] + wsum[4 * k + 2] + wsum[4 * k + 3];
        float scale = n / (1.0f + n) / sqrtf(n + 1e-9f);
        capv = scale * v;
        if (!half) cap_s[off] = capv;
        __syncthreads();

        if (it < 2) {
            // cw[k,c] += hat[c, k*64:]. cap[k,:]
            for (int idx = tid; idx < NI_ * nact; idx += 512) {
                int kk = idx / nact, c = idx - kk * nact;
                const float* hr = &hat_s[c * HPAD + kk * 64];
                const float* cr = &cap_s[kk * 64];
                float dsum = 0.f;
                #pragma unroll 8
                for (int dd = 0; dd < 64; ++dd) dsum += hr[dd] * cr[dd];
                cw_s[kk * S_ + c] += dsum;
            }
            __syncthreads();
        }
    }

    if (!half) out_interest[(size_t)b * E_ + off] = capv;
}

// ====================================================================
// launch — adj runs concurrently with hat+route on a second stream
// ====================================================================
extern "C" void kernel_launch(void* const* d_in, const int* in_sizes, int n_in,
                              void* d_out, int out_size)
{
    const int*   uid      = (const int*)  d_in[0];
    const int*   age      = (const int*)  d_in[1];
    const int*   gender   = (const int*)  d_in[2];
    const int*   occup    = (const int*)  d_in[3];
    const int*   mid_his  = (const int*)  d_in[4];
    const float* mask     = (const float*)d_in[5];
    const float* ue       = (const float*)d_in[6];
    const float* at       = (const float*)d_in[7];
    const float* gt       = (const float*)d_in[8];
    const float* ot       = (const float*)d_in[9];
    const float* mid_emb  = (const float*)d_in[10];
    const float* w        = (const float*)d_in[11];
    float* out = (float*)d_out;

    static cudaStream_t s2 = nullptr;
    static cudaEvent_t ev_fork = nullptr, ev_join = nullptr;
    if (!s2) {
        cudaStreamCreateWithFlags(&s2, cudaStreamNonBlocking);
        cudaEventCreateWithFlags(&ev_fork, cudaEventDisableTiming);
        cudaEventCreateWithFlags(&ev_join, cudaEventDisableTiming);
        cudaFuncSetAttribute(route_kernel,
                             cudaFuncAttributeMaxDynamicSharedMemorySize, ROUTE_SMEM);
        cudaFuncSetAttribute(adj_kernel,
                             cudaFuncAttributeMaxDynamicSharedMemorySize, SMEM_GEMM_BYTES);
        cudaFuncSetAttribute(hat_kernel,
                             cudaFuncAttributeMaxDynamicSharedMemorySize, SMEM_GEMM_BYTES);
    }

    uprof_kernel<<<B_ * D_ / 256, 256>>>(uid, age, gender, occup, ue, at, gt, ot);
    gather_kernel<<<B_ * S_ * 16 / 256, 256>>>(mid_his, mask, mid_emb);

    cudaEventRecord(ev_fork, 0);
    cudaStreamWaitEvent(s2, ev_fork, 0);

    hat_kernel<<<dim3(2, B_ / 128, S_), 256, SMEM_GEMM_BYTES, s2>>>(w);
    route_kernel<<<B_, 512, ROUTE_SMEM, s2>>>(mask, out);

    adj_kernel<<<dim3(2, 2, B_), 256, SMEM_GEMM_BYTES>>>(mask, out + INTEREST_ELEMS);

    cudaEventRecord(ev_join, s2);
    cudaStreamWaitEvent(0, ev_join, 0);
}

// round 8
// speedup vs baseline: 2.1429x; 1.1511x over previous
#include <cuda_runtime.h>
#include <cstdint>

// ---------------- problem constants ----------------
#define B_   1024
#define S_   200
#define D_   64
#define NI_  4
#define E_   256            // NI * D
#define INTEREST_ELEMS (B_ * NI_ * D_)   // 262144, adj follows at this offset

// ---------------- device scratch (static; no runtime alloc) ----------------
__device__ float g_uprof[B_ * D_];                       // 256 KB
__device__ float g_item[(long long)B_ * S_ * D_];        // 52.4 MB
__device__ float g_hat [(long long)S_ * B_ * E_];        // 209.7 MB, [s][rank][e]
__device__ int   g_cnt [S_];                             // active-b count per s
__device__ int   g_blist[S_ * B_];                       // [s][rank] -> b
__device__ int   g_rank [S_ * B_];                       // [s][b] -> rank

// ---------------- cp.async helpers ----------------
#define CP_ASYNC16(dst_u32, src_ptr) \
    asm volatile("cp.async.cg.shared.global [%0], [%1], 16;" \
                 :: "r"(dst_u32), "l"(src_ptr))
#define CP_COMMIT_WAIT() \
    asm volatile("cp.async.commit_group;\ncp.async.wait_group 0;" ::: "memory")

// ---------------- tf32 mma helpers ----------------
__device__ __forceinline__ uint32_t f2tf(float x) {
    uint32_t u;
    asm("cvt.rna.tf32.f32 %0, %1;" : "=r"(u) : "f"(x));
    return u;
}

__device__ __forceinline__ void mma8(float* d, const uint32_t* a,
                                     uint32_t b0, uint32_t b1) {
    asm volatile(
        "mma.sync.aligned.m16n8k8.row.col.f32.tf32.tf32.f32 "
        "{%0,%1,%2,%3}, {%4,%5,%6,%7}, {%8,%9}, {%0,%1,%2,%3};"
        : "+f"(d[0]), "+f"(d[1]), "+f"(d[2]), "+f"(d[3])
        : "r"(a[0]), "r"(a[1]), "r"(a[2]), "r"(a[3]), "r"(b0), "r"(b1));
}

#define LDA 68     // smem row stride (uint32); conflict-free fragment LDS
#define SMEM_GEMM_BYTES (2 * 128 * LDA * 4)   // 69632

// 128x128x64 block tile, 8 warps of 32x64 each.
__device__ __forceinline__ void mma_core(const uint32_t* __restrict__ As,
                                         const uint32_t* __restrict__ Bs,
                                         int tid, float acc[2][8][4]) {
    const int lane = tid & 31, wid = tid >> 5;
    const int g = lane >> 2, t = lane & 3;
    const int m0 = (wid & 3) * 32, n0 = (wid >> 2) * 64;
    #pragma unroll
    for (int k0 = 0; k0 < 64; k0 += 8) {
        uint32_t a[2][4];
        #pragma unroll
        for (int mf = 0; mf < 2; ++mf) {
            const uint32_t* p = As + (m0 + 16 * mf + g) * LDA + k0 + t;
            a[mf][0] = p[0];
            a[mf][1] = p[8 * LDA];
            a[mf][2] = p[4];
            a[mf][3] = p[8 * LDA + 4];
        }
        #pragma unroll
        for (int nf = 0; nf < 8; ++nf) {
            const uint32_t* p = Bs + (n0 + 8 * nf + g) * LDA + k0 + t;
            uint32_t b0v = p[0], b1v = p[4];
            mma8(acc[0][nf], a[0], b0v, b1v);
            mma8(acc[1][nf], a[1], b0v, b1v);
        }
    }
}

// ====================================================================
// K1: user profile (+ zero the per-s active counters)
// ====================================================================
__global__ __launch_bounds__(256) void uprof_kernel(
    const int* __restrict__ uid, const int* __restrict__ age,
    const int* __restrict__ gender, const int* __restrict__ occup,
    const float* __restrict__ ue, const float* __restrict__ at,
    const float* __restrict__ gt, const float* __restrict__ ot)
{
    if (blockIdx.x == 0 && threadIdx.x < S_) g_cnt[threadIdx.x] = 0;
    int idx = blockIdx.x * 256 + threadIdx.x;
    int b = idx >> 6, d = idx & 63;
    float v = ue[(size_t)uid[b]    * 64 + d]
            + gt[(size_t)gender[b] * 64 + d]
            + at[(size_t)age[b]    * 64 + d]
            + ot[(size_t)occup[b]  * 64 + d];
    g_uprof[idx] = 0.25f * v;
}

// ====================================================================
// K2: item_his = mid_emb[mid_his]*mask  (+ build per-s active-b lists)
//     rank order is atomic (nondeterministic) but affects only the
//     intermediate layout; every summed value is permutation-invariant.
// ====================================================================
__global__ __launch_bounds__(256) void gather_kernel(
    const int* __restrict__ mid_his, const float* __restrict__ mask,
    const float* __restrict__ mid_emb)
{
    int t  = blockIdx.x * 256 + threadIdx.x;
    int bs = t >> 4, q = t & 15;
    int mi = mid_his[bs];
    float m = mask[bs];
    float4 e = ((const float4*)mid_emb)[(size_t)mi * 16 + q];
    float4 it;
    it.x = e.x * m;  it.y = e.y * m;  it.z = e.z * m;  it.w = e.w * m;
    ((float4*)g_item)[(size_t)bs * 16 + q] = it;

    if (q == 0 && m != 0.f) {
        int b = bs / S_, s = bs - b * S_;
        int r = atomicAdd(&g_cnt[s], 1);
        g_blist[s * B_ + r] = b;
        g_rank [s * B_ + b] = r;
    }
}

// ====================================================================
// K3: adj — tf32 tensor cores, tile 128x128, grid (2,2,B)
// ====================================================================
__global__ __launch_bounds__(256) void adj_kernel(
    const float* __restrict__ mask, float* __restrict__ out)
{
    extern __shared__ uint32_t sh[];
    uint32_t* As = sh;
    uint32_t* Bs = sh + 128 * LDA;
    __shared__ float msk[256];

    const int b  = blockIdx.z;
    const int i0 = blockIdx.y * 128;
    const int j0 = blockIdx.x * 128;
    const int tid = threadIdx.x;
    const float* It = g_item + (size_t)b * (S_ * D_);

    msk[tid] = (tid < S_) ? mask[b * S_ + tid] : 0.f;

    #pragma unroll
    for (int p = 0; p < 8; ++p) {
        int q = tid + p * 256;
        int r = q >> 4, c4 = q & 15;
        float4 up = ((const float4*)g_uprof)[b * 16 + c4];
        float4 av = make_float4(0.f, 0.f, 0.f, 0.f);
        float4 bv = make_float4(0.f, 0.f, 0.f, 0.f);
        if (i0 + r < S_) {
            float4 iv = *(const float4*)(It + (size_t)(i0 + r) * 64 + c4 * 4);
            av.x = iv.x * up.x; av.y = iv.y * up.y;
            av.z = iv.z * up.z; av.w = iv.w * up.w;
        }
        if (j0 + r < S_) bv = *(const float4*)(It + (size_t)(j0 + r) * 64 + c4 * 4);
        uint4 at4 = make_uint4(f2tf(av.x), f2tf(av.y), f2tf(av.z), f2tf(av.w));
        uint4 bt4 = make_uint4(f2tf(bv.x), f2tf(bv.y), f2tf(bv.z), f2tf(bv.w));
        *(uint4*)(As + r * LDA + c4 * 4) = at4;
        *(uint4*)(Bs + r * LDA + c4 * 4) = bt4;
    }
    __syncthreads();

    float acc[2][8][4] = {};
    mma_core(As, Bs, tid, acc);

    const int lane = tid & 31, wid = tid >> 5;
    const int g = lane >> 2, t = lane & 3;
    const int m0 = (wid & 3) * 32, n0 = (wid >> 2) * 64;
    float* outb = out + (size_t)b * (S_ * S_);

    #pragma unroll
    for (int mf = 0; mf < 2; ++mf) {
        #pragma unroll
        for (int nf = 0; nf < 8; ++nf) {
            int i = i0 + m0 + 16 * mf + g;
            int j = j0 + n0 + 8 * nf + 2 * t;
            if (j < S_) {
                float mj0 = msk[j], mj1 = msk[j + 1];
                if (i < S_) {
                    float mi = msk[i];
                    float s0 = 1.f / (1.f + __expf(-acc[mf][nf][0]));
                    float s1 = 1.f / (1.f + __expf(-acc[mf][nf][1]));
                    *(float2*)(outb + (size_t)i * S_ + j) =
                        make_float2(s0 * mi * mj0, s1 * mi * mj1);
                }
                if (i + 8 < S_) {
                    float mi = msk[i + 8];
                    float s2 = 1.f / (1.f + __expf(-acc[mf][nf][2]));
                    float s3 = 1.f / (1.f + __expf(-acc[mf][nf][3]));
                    *(float2*)(outb + (size_t)(i + 8) * S_ + j) =
                        make_float2(s2 * mi * mj0, s3 * mi * mj1);
                }
            }
        }
    }
}

// ====================================================================
// K4: hat — tf32 tensor cores, ACTIVE b-rows only, compacted output.
//     grid (2, 8, S); blocks past cnt[s] exit immediately.
// ====================================================================
__global__ __launch_bounds__(256) void hat_kernel(const float* __restrict__ w)
{
    const int s   = blockIdx.z;
    const int cnt = g_cnt[s];
    const int b0  = blockIdx.y * 128;
    if (b0 >= cnt) return;
    const int e0  = blockIdx.x * 128;
    const int tid = threadIdx.x;

    extern __shared__ uint32_t sh[];
    uint32_t* As = sh;
    uint32_t* Bs = sh + 128 * LDA;

    #pragma unroll
    for (int p = 0; p < 8; ++p) {
        int q = tid + p * 256;
        int r = q >> 4, c4 = q & 15;
        float4 av = make_float4(0.f, 0.f, 0.f, 0.f);
        if (b0 + r < cnt) {
            int bidx = g_blist[s * B_ + b0 + r];
            av = *(const float4*)(g_item + ((size_t)bidx * S_ + s) * 64 + c4 * 4);
        }
        float4 bv = *(const float4*)(w + ((size_t)s * E_ + (e0 + r)) * 64 + c4 * 4);
        uint4 at4 = make_uint4(f2tf(av.x), f2tf(av.y), f2tf(av.z), f2tf(av.w));
        uint4 bt4 = make_uint4(f2tf(bv.x), f2tf(bv.y), f2tf(bv.z), f2tf(bv.w));
        *(uint4*)(As + r * LDA + c4 * 4) = at4;
        *(uint4*)(Bs + r * LDA + c4 * 4) = bt4;
    }
    __syncthreads();

    float acc[2][8][4] = {};
    mma_core(As, Bs, tid, acc);

    const int lane = tid & 31, wid = tid >> 5;
    const int g = lane >> 2, t = lane & 3;
    const int m0 = (wid & 3) * 32, n0 = (wid >> 2) * 64;

    #pragma unroll
    for (int mf = 0; mf < 2; ++mf) {
        #pragma unroll
        for (int nf = 0; nf < 8; ++nf) {
            int ri = b0 + m0 + 16 * mf + g;
            int e  = e0 + n0 + 8 * nf + 2 * t;
            if (ri < cnt)
                *(float2*)(g_hat + ((size_t)s * B_ + ri) * E_ + e) =
                    make_float2(acc[mf][nf][0], acc[mf][nf][1]);
            if (ri + 8 < cnt)
                *(float2*)(g_hat + ((size_t)s * B_ + ri + 8) * E_ + e) =
                    make_float2(acc[mf][nf][2], acc[mf][nf][3]);
        }
    }
}

// ====================================================================
// K5: routing, fused, 512 threads, mask-compacted rows fetched via
//     rank map with cp.async (high-MLP bulk load).
// ====================================================================
#define HPAD 260   // floats per smem row: 16B-aligned dsts; 4 banks/row step
#define ROUTE_SMEM (S_ * HPAD * 4)   // 208000 B
__global__ __launch_bounds__(512) void route_kernel(
    const float* __restrict__ mask, float* __restrict__ out_interest)
{
    extern __shared__ float hat_s[];                 // [nact][260]
    __shared__ float cw_s[NI_ * S_];
    __shared__ float sw_s[NI_ * S_];
    __shared__ float cap_s[E_];
    __shared__ float wsum[16];
    __shared__ int   act[S_];
    __shared__ int   act_row[S_];
    __shared__ int   wtot[16];
    __shared__ int   nact_s;

    const int b = blockIdx.x;
    const int tid = threadIdx.x;
    const int lane = tid & 31, wrp = tid >> 5;

    // ---- deterministic compaction of active s (mask != 0) ----
    int pred = (tid < S_) ? (mask[b * S_ + tid] != 0.f) : 0;
    unsigned bal = __ballot_sync(0xffffffffu, pred);
    if (lane == 0) wtot[wrp] = __popc(bal);
    __syncthreads();
    int prefix = 0;
    for (int i = 0; i < wrp; ++i) prefix += wtot[i];
    if (pred) act[prefix + __popc(bal & ((1u << lane) - 1u))] = tid;
    if (tid == 0) {
        int t = 0;
        for (int i = 0; i < 7; ++i) t += wtot[i];
        nact_s = t;
    }
    __syncthreads();
    const int nact = nact_s;

    // ---- resolve compacted global row index per active s ----
    for (int c = tid; c < nact; c += 512) {
        int s = act[c];
        act_row[c] = s * B_ + g_rank[s * B_ + b];
    }
    for (int x = tid; x < NI_ * S_; x += 512) cw_s[x] = 0.f;
    __syncthreads();

    // ---- bulk cp.async load of active hat rows into smem ----
    uint32_t smem_b = (uint32_t)__cvta_generic_to_shared(hat_s);
    for (int x4 = tid; x4 < nact * 64; x4 += 512) {
        int c = x4 >> 6, e4 = (x4 & 63) << 2;
        const float* src = g_hat + ((size_t)act_row[c] << 8) + e4;
        CP_ASYNC16(smem_b + (uint32_t)(c * HPAD + e4) * 4, src);
    }
    CP_COMMIT_WAIT();
    __syncthreads();

    const int k = tid >> 7;           // 0..3
    const int d = (tid >> 1) & 63;    // pair shares d
    const int half = tid & 1;
    const int off = k * 64 + d;
    const int hn = (nact + 1) >> 1;
    float capv = 0.f;

    for (int it = 0; it < 3; ++it) {
        if (tid < nact) {
            float c0 = cw_s[0 * S_ + tid], c1 = cw_s[1 * S_ + tid];
            float c2 = cw_s[2 * S_ + tid], c3 = cw_s[3 * S_ + tid];
            float mx = fmaxf(fmaxf(c0, c1), fmaxf(c2, c3));
            float e0 = __expf(c0 - mx), e1 = __expf(c1 - mx);
            float e2 = __expf(c2 - mx), e3 = __expf(c3 - mx);
            float inv = 1.0f / (e0 + e1 + e2 + e3);
            sw_s[0 * S_ + tid] = e0 * inv;
            sw_s[1 * S_ + tid] = e1 * inv;
            sw_s[2 * S_ + tid] = e2 * inv;
            sw_s[3 * S_ + tid] = e3 * inv;
        }
        __syncthreads();

        // v[k,d] = sum_c sw[k,c]*hat[c, k*64+d]; c-range split across pair
        float v = 0.f;
        const float* swk = &sw_s[k * S_];
        const int cbeg = half * hn;
        const int cend = (cbeg + hn < nact) ? cbeg + hn : nact;
        #pragma unroll 4
        for (int c = cbeg; c < cend; ++c)
            v += swk[c] * hat_s[c * HPAD + off];
        v += __shfl_xor_sync(0xffffffffu, v, 1);     // both halves: full sum

        float p = half ? 0.f : v * v;
        #pragma unroll
        for (int o = 16; o; o >>= 1) p += __shfl_xor_sync(0xffffffffu, p, o);
        if (lane == 0) wsum[wrp] = p;
        __syncthreads();
        float n = wsum[4 * k] + wsum[4 * k + 1] + wsum[4 * k + 2] + wsum[4 * k + 3];
        float scale = n / (1.0f + n) / sqrtf(n + 1e-9f);
        capv = scale * v;
        if (!half) cap_s[off] = capv;
        __syncthreads();

        if (it < 2) {
            // cw[k,c] += hat[c, k*64:]. cap[k,:]
            for (int idx = tid; idx < NI_ * nact; idx += 512) {
                int kk = idx / nact, c = idx - kk * nact;
                const float* hr = &hat_s[c * HPAD + kk * 64];
                const float* cr = &cap_s[kk * 64];
                float dsum = 0.f;
                #pragma unroll 8
                for (int dd = 0; dd < 64; ++dd) dsum += hr[dd] * cr[dd];
                cw_s[kk * S_ + c] += dsum;
            }
            __syncthreads();
        }
    }

    if (!half) out_interest[(size_t)b * E_ + off] = capv;
}

// ====================================================================
// launch — adj runs concurrently with hat+route on a second stream
// ====================================================================
extern "C" void kernel_launch(void* const* d_in, const int* in_sizes, int n_in,
                              void* d_out, int out_size)
{
    const int*   uid      = (const int*)  d_in[0];
    const int*   age      = (const int*)  d_in[1];
    const int*   gender   = (const int*)  d_in[2];
    const int*   occup    = (const int*)  d_in[3];
    const int*   mid_his  = (const int*)  d_in[4];
    const float* mask     = (const float*)d_in[5];
    const float* ue       = (const float*)d_in[6];
    const float* at       = (const float*)d_in[7];
    const float* gt       = (const float*)d_in[8];
    const float* ot       = (const float*)d_in[9];
    const float* mid_emb  = (const float*)d_in[10];
    const float* w        = (const float*)d_in[11];
    float* out = (float*)d_out;

    static cudaStream_t s2 = nullptr;
    static cudaEvent_t ev_fork = nullptr, ev_join = nullptr;
    if (!s2) {
        cudaStreamCreateWithFlags(&s2, cudaStreamNonBlocking);
        cudaEventCreateWithFlags(&ev_fork, cudaEventDisableTiming);
        cudaEventCreateWithFlags(&ev_join, cudaEventDisableTiming);
        cudaFuncSetAttribute(route_kernel,
                             cudaFuncAttributeMaxDynamicSharedMemorySize, ROUTE_SMEM);
        cudaFuncSetAttribute(adj_kernel,
                             cudaFuncAttributeMaxDynamicSharedMemorySize, SMEM_GEMM_BYTES);
        cudaFuncSetAttribute(hat_kernel,
                             cudaFuncAttributeMaxDynamicSharedMemorySize, SMEM_GEMM_BYTES);
    }

    uprof_kernel<<<B_ * D_ / 256, 256>>>(uid, age, gender, occup, ue, at, gt, ot);
    gather_kernel<<<B_ * S_ * 16 / 256, 256>>>(mid_his, mask, mid_emb);

    cudaEventRecord(ev_fork, 0);
    cudaStreamWaitEvent(s2, ev_fork, 0);

    hat_kernel<<<dim3(2, B_ / 128, S_), 256, SMEM_GEMM_BYTES, s2>>>(w);
    route_kernel<<<B_, 512, ROUTE_SMEM, s2>>>(mask, out);

    adj_kernel<<<dim3(2, 2, B_), 256, SMEM_GEMM_BYTES>>>(mask, out + INTEREST_ELEMS);

    cudaEventRecord(ev_join, s2);
    cudaStreamWaitEvent(0, ev_join, 0);
}